// round 14
// baseline (speedup 1.0000x reference)
#include <cuda_runtime.h>
#include <cuda_bf16.h>
#include <math.h>
#include <float.h>
#include <stdint.h>

// Gate_33827162423867 — fused HMMA router, LARGE-REQUEST bulk-async edition.
// Theory: all prior variants were bound by per-SM per-REQUEST cost of the
// load path (~46cyc/bulk request; LDGSTS/LDG issue floors), not bytes.
// This version: TB=64 tokens/CTA, each bulk request = 1KB of one token's row
// (4 K-chunks at once) -> 68 requests per 4 chunks instead of 516.
// bf16 2-split (3 products, fp32 accum, mma.sync) -> FTZ softmax -> top-8;
// knife-edge tokens recomputed exactly in-CTA (split-K4 fold).
// Output: d_out float*, [0,T*8) gate weights, [T*8, 2*T*8) indices-as-float.

#define NE    64
#define TB    64
#define KCH   64
#define NT    256
#define TOPK  8

#define EPS_GAP 0.01f
#define EPS_B   0.01f
#define LN_FLT_MIN -87.33654475055310898657124730373f

#define RS    72       // bf16 x-tile row stride (elements); 144B rows
#define SSTR  65
#define FSTR  73
#define MAXFLAG 32

// smem layout (bytes)
#define XSTRB 1040                       // raw x row: 1KB data + 16B stagger
#define XRS   (TB * XSTRB)               // 66560 per stage
#define XR(s) ((s) * XRS)
#define WOFF  (2 * XRS)                  // 133120
#define WR(s) (WOFF + (s) * 16384)       // 3-stage w ring (hi 8KB + lo 8KB)
#define SM_XH (WOFF + 3 * 16384)         // 182272
#define SM_XL (SM_XH + 9216)             // 191488
#define SMEM_DYN (SM_XL + 9216)          // 200704
#define EXPECT_X 65536
#define EXPECT_W 16384
#define SM_FIX 65536                     // fixup rows alias x-ring (post-GEMM)

// pre-converted w tiles: 64 chunks x (8KB hi + 8KB lo), swizzled 128B rows
__device__ __align__(16) unsigned char g_wtiles[64 * 16384];

// ---------------- helpers ----------------
__device__ __forceinline__ uint32_t smem_u32(const void* p) {
    uint32_t a;
    asm("{ .reg .u64 t; cvta.to.shared.u64 t, %1; cvt.u32.u64 %0, t; }"
        : "=r"(a) : "l"(p));
    return a;
}
__device__ __forceinline__ uint32_t swz128(uint32_t b) {
    return b ^ ((b >> 3) & 0x70);
}
__device__ __forceinline__ uint32_t cvt_bf16x2(float lo, float hi) {
    uint32_t r;
    asm("cvt.rn.bf16x2.f32 %0, %1, %2;" : "=r"(r) : "f"(hi), "f"(lo));
    return r;
}
__device__ __forceinline__ float bflo_f(uint32_t h) { return __uint_as_float(h << 16); }
__device__ __forceinline__ float bfhi_f(uint32_t h) { return __uint_as_float(h & 0xFFFF0000u); }

__device__ __forceinline__ void mbar_init(uint32_t a, uint32_t cnt) {
    asm volatile("mbarrier.init.shared.b64 [%0], %1;" :: "r"(a), "r"(cnt) : "memory");
}
__device__ __forceinline__ void mbar_expect(uint32_t a, uint32_t bytes) {
    asm volatile("mbarrier.arrive.expect_tx.shared.b64 _, [%0], %1;"
                 :: "r"(a), "r"(bytes) : "memory");
}
__device__ __forceinline__ void mbar_wait(uint32_t a, uint32_t parity) {
    asm volatile(
        "{\n\t.reg .pred P1;\n\t"
        "WAIT_%=:\n\t"
        "mbarrier.try_wait.parity.acquire.cta.shared::cta.b64 P1, [%0], %1, 0x989680;\n\t"
        "@P1 bra.uni DONE_%=;\n\t"
        "bra.uni WAIT_%=;\n\t"
        "DONE_%=:\n\t}"
        :: "r"(a), "r"(parity) : "memory");
}
__device__ __forceinline__ void bulk_g2s(uint32_t dst, const void* src,
                                         uint32_t bytes, uint32_t mbar) {
    asm volatile(
        "cp.async.bulk.shared::cta.global.mbarrier::complete_tx::bytes "
        "[%0], [%1], %2, [%3];"
        :: "r"(dst), "l"(src), "r"(bytes), "r"(mbar) : "memory");
}
__device__ __forceinline__ void ldm_x4(uint32_t addr, uint32_t& r0, uint32_t& r1,
                                       uint32_t& r2, uint32_t& r3) {
    asm volatile("ldmatrix.sync.aligned.m8n8.x4.shared.b16 {%0,%1,%2,%3}, [%4];"
                 : "=r"(r0), "=r"(r1), "=r"(r2), "=r"(r3) : "r"(addr));
}
__device__ __forceinline__ void mma_bf16(float* d, uint32_t a0, uint32_t a1,
                                         uint32_t a2, uint32_t a3,
                                         uint32_t b0, uint32_t b1) {
    asm volatile(
        "mma.sync.aligned.m16n8k16.row.col.f32.bf16.bf16.f32 "
        "{%0,%1,%2,%3}, {%4,%5,%6,%7}, {%8,%9}, {%0,%1,%2,%3};"
        : "+f"(d[0]), "+f"(d[1]), "+f"(d[2]), "+f"(d[3])
        : "r"(a0), "r"(a1), "r"(a2), "r"(a3), "r"(b0), "r"(b1));
}

// ================= prep kernel: w -> swizzled bf16 hi/lo tiles =================
__global__ __launch_bounds__(256)
void prep_w_kernel(const float* __restrict__ w, int dim)
{
    // task: chunk c (64) x expert e (64) x 16B-block kb (8)
    int task = blockIdx.x * 256 + threadIdx.x;       // 0..32767
    int kb = task & 7;
    int e  = (task >> 3) & 63;
    int c  = task >> 9;
    const float* src = w + (size_t)e * dim + c * KCH + kb * 8;
    float v[8];
    #pragma unroll
    for (int i = 0; i < 8; i++) v[i] = src[i];
    uint32_t h[4], l[4];
    #pragma unroll
    for (int i = 0; i < 4; i++) {
        h[i] = cvt_bf16x2(v[2 * i], v[2 * i + 1]);
        l[i] = cvt_bf16x2(v[2 * i] - bflo_f(h[i]), v[2 * i + 1] - bfhi_f(h[i]));
    }
    uint32_t off = swz128((uint32_t)(e * 128 + kb * 16));
    unsigned char* base = g_wtiles + (size_t)c * 16384;
    *reinterpret_cast<uint4*>(base + off)        = make_uint4(h[0], h[1], h[2], h[3]);
    *reinterpret_cast<uint4*>(base + 8192 + off) = make_uint4(l[0], l[1], l[2], l[3]);
}

// ================= main fused kernel =================
__global__ __launch_bounds__(NT, 1)
void gate_kernel(const float* __restrict__ x,
                 const float* __restrict__ w,
                 float* __restrict__ out,
                 int dim, int tokens)
{
    extern __shared__ char dyn[];
    __shared__ __align__(8) uint64_t s_mbx[2];
    __shared__ __align__(8) uint64_t s_mbw[3];
    __shared__ int   s_nflag;
    __shared__ int   s_flags[MAXFLAG];
    __shared__ float s_part[2][4 * NE];

    const uint32_t sbase = smem_u32(dyn);
    const int tid  = threadIdx.x;
    const int wid  = tid >> 5;
    const int lane = tid & 31;
    const int token0 = blockIdx.x * TB;
    const int nchunks = dim / KCH;       // 64
    const int nsuper  = nchunks / 4;     // 16

    if (tid == 0) {
        s_nflag = 0;
        #pragma unroll
        for (int s = 0; s < 2; s++) mbar_init(smem_u32(&s_mbx[s]), 1);
        #pragma unroll
        for (int s = 0; s < 3; s++) mbar_init(smem_u32(&s_mbw[s]), 1);
        asm volatile("fence.proxy.async.shared::cta;" ::: "memory");
    }
    __syncthreads();

    uint32_t mbx[2] = { smem_u32(&s_mbx[0]), smem_u32(&s_mbx[1]) };
    uint32_t mbw[3] = { smem_u32(&s_mbw[0]), smem_u32(&s_mbw[1]), smem_u32(&s_mbw[2]) };

    // one 1KB request per token row for super-chunk sc
    auto issue_x = [&](int sc) {
        const int s = sc & 1;
        if (tid < TB) {
            bulk_g2s(sbase + XR(s) + tid * XSTRB,
                     x + (size_t)(token0 + tid) * dim + sc * 256, 1024, mbx[s]);
        } else if (tid == TB) {
            mbar_expect(mbx[s], EXPECT_X);
        }
    };
    // one 16KB request per chunk for w
    auto issue_w = [&](int c) {
        if (tid == TB + 1) {
            bulk_g2s(sbase + WR(c % 3), g_wtiles + (size_t)c * 16384, 16384, mbw[c % 3]);
        } else if (tid == TB + 2) {
            mbar_expect(mbw[c % 3], EXPECT_W);
        }
    };

    // prologue
    issue_x(0); issue_x(1);
    issue_w(0); issue_w(1);

    // convert mapping: thread -> row (tid&63), float group (tid>>6)*16
    const int crow = tid & 63;
    const int cg   = tid >> 6;           // 0..3

    // MMA lane constants: warp = 16 tokens x 32 experts
    const int tg   = wid & 3;
    const int eh   = wid >> 2;
    const int tokb = tg * 16;
    const uint32_t aoff = (uint32_t)((tokb + (lane & 7) + (((lane >> 3) & 1) * 8)) * (RS * 2)
                                     + ((lane >> 4) * 16));
    const int e_local = (lane & 7) + ((lane >> 4) << 3);
    const int colb    = ((lane >> 3) & 1) * 16;

    float acc[4][4];
    #pragma unroll
    for (int n = 0; n < 4; n++)
        #pragma unroll
        for (int i = 0; i < 4; i++) acc[n][i] = 0.0f;

    int phx[2] = {0, 0};
    int phw[3] = {0, 0, 0};

    for (int sc = 0; sc < nsuper; sc++) {
        const int sx = sc & 1;
        mbar_wait(mbx[sx], phx[sx]); phx[sx] ^= 1;

        #pragma unroll
        for (int sub = 0; sub < 4; sub++) {
            const int c  = sc * 4 + sub;
            const int sw = c % 3;
            mbar_wait(mbw[sw], phw[sw]); phw[sw] ^= 1;
            __syncthreads();   // retire chunk c-1 MMA: xh/xl + w stage (c+2)%3 free

            if (c + 2 < nchunks) issue_w(c + 2);

            // ---- convert: 16 floats/thread of chunk c from raw x ----
            {
                const char* raw = dyn + XR(sx) + crow * XSTRB + sub * 256 + cg * 64;
                char* xh = dyn + SM_XH + crow * (RS * 2) + cg * 32;
                char* xl = dyn + SM_XL + crow * (RS * 2) + cg * 32;
                #pragma unroll
                for (int jj = 0; jj < 2; jj++) {       // 8 floats per iter
                    float4 a = *reinterpret_cast<const float4*>(raw + jj * 32);
                    float4 b = *reinterpret_cast<const float4*>(raw + jj * 32 + 16);
                    uint32_t h0 = cvt_bf16x2(a.x, a.y);
                    uint32_t h1 = cvt_bf16x2(a.z, a.w);
                    uint32_t h2 = cvt_bf16x2(b.x, b.y);
                    uint32_t h3 = cvt_bf16x2(b.z, b.w);
                    uint32_t l0 = cvt_bf16x2(a.x - bflo_f(h0), a.y - bfhi_f(h0));
                    uint32_t l1 = cvt_bf16x2(a.z - bflo_f(h1), a.w - bfhi_f(h1));
                    uint32_t l2 = cvt_bf16x2(b.x - bflo_f(h2), b.y - bfhi_f(h2));
                    uint32_t l3 = cvt_bf16x2(b.z - bflo_f(h3), b.w - bfhi_f(h3));
                    *reinterpret_cast<uint4*>(xh + jj * 16) = make_uint4(h0, h1, h2, h3);
                    *reinterpret_cast<uint4*>(xl + jj * 16) = make_uint4(l0, l1, l2, l3);
                }
            }
            __syncthreads();               // bf16 tiles ready

            // refill the x stage as soon as its last sub is consumed
            if (sub == 3 && sc + 2 < nsuper) issue_x(sc + 2);

            // ---- MMA: 4 k-steps x 2 expert-pairs x 3 products ----
            const uint32_t wbase = sbase + WR(sw);
            #pragma unroll
            for (int ks = 0; ks < 4; ks++) {
                const uint32_t kb = (uint32_t)(ks * 32);
                uint32_t ah0, ah1, ah2, ah3, al0, al1, al2, al3;
                ldm_x4(sbase + SM_XH + aoff + kb, ah0, ah1, ah2, ah3);
                ldm_x4(sbase + SM_XL + aoff + kb, al0, al1, al2, al3);
                #pragma unroll
                for (int q = 0; q < 2; q++) {
                    const int p = 2 * eh + q;
                    uint32_t off = swz128((uint32_t)((p * 16 + e_local) * 128) + kb + (uint32_t)colb);
                    uint32_t bh0, bh1, bh2, bh3, bl0, bl1, bl2, bl3;
                    ldm_x4(wbase + off, bh0, bh1, bh2, bh3);
                    ldm_x4(wbase + 8192 + off, bl0, bl1, bl2, bl3);
                    mma_bf16(acc[2 * q], ah0, ah1, ah2, ah3, bh0, bh1);
                    mma_bf16(acc[2 * q], ah0, ah1, ah2, ah3, bl0, bl1);
                    mma_bf16(acc[2 * q], al0, al1, al2, al3, bh0, bh1);
                    mma_bf16(acc[2 * q + 1], ah0, ah1, ah2, ah3, bh2, bh3);
                    mma_bf16(acc[2 * q + 1], ah0, ah1, ah2, ah3, bl2, bl3);
                    mma_bf16(acc[2 * q + 1], al0, al1, al2, al3, bh2, bh3);
                }
            }
        }
    }

    __syncthreads();

    // ---- accumulators -> padded smem scores [64][SSTR] (aliases x-ring) ----
    float* scores = reinterpret_cast<float*>(dyn);
    {
        const int g  = lane >> 2;
        const int t2 = (lane & 3) * 2;
        #pragma unroll
        for (int n = 0; n < 4; n++) {
            const int col = eh * 32 + n * 8 + t2;
            scores[(tokb + g) * SSTR + col]         = acc[n][0];
            scores[(tokb + g) * SSTR + col + 1]     = acc[n][1];
            scores[(tokb + g + 8) * SSTR + col]     = acc[n][2];
            scores[(tokb + g + 8) * SSTR + col + 1] = acc[n][3];
        }
    }
    __syncthreads();

    // ---- fast epilogue: 1 thread per token ----
    if (tid < TB) {
        float* srow = scores + tid * SSTR;
        float m = -FLT_MAX;
        #pragma unroll
        for (int e = 0; e < NE; e++) m = fmaxf(m, srow[e]);

        float denom = 0.0f;
        #pragma unroll
        for (int e = 0; e < NE; e++) {
            float q = __expf(srow[e] - m);
            if (q < FLT_MIN) q = 0.0f;
            denom += q;
        }

        bool flag = false;
        float b2 = LN_FLT_MIN + __logf(denom);
        #pragma unroll
        for (int e = 0; e < NE; e++) {
            float d = srow[e] - m;
            if (fabsf(d - LN_FLT_MIN) < EPS_B || fabsf(d - b2) < EPS_B) flag = true;
        }
        {
            unsigned long long used = 0ull;
            float prevv = 0.0f;
            for (int j = 0; j < 9; j++) {
                float best = -FLT_MAX; int bi = 0;
                for (int e = 0; e < NE; e++)
                    if (!((used >> e) & 1ull) && srow[e] > best) { best = srow[e]; bi = e; }
                used |= 1ull << bi;
                if (j > 0 && (prevv - best) < EPS_GAP) flag = true;
                prevv = best;
            }
        }

        float inv = 1.0f / denom;
        #pragma unroll
        for (int e = 0; e < NE; e++) {
            float q = __expf(srow[e] - m);
            if (q < FLT_MIN) q = 0.0f;
            q *= inv;
            if (q < FLT_MIN) q = 0.0f;
            srow[e] = q;
        }

        const int tglob = token0 + tid;
        float* out_w   = out + (size_t)tglob * TOPK;
        float* out_idx = out + (size_t)tokens * TOPK + (size_t)tglob * TOPK;
        #pragma unroll
        for (int j = 0; j < TOPK; j++) {
            float best = -1.0f; int bi = 0;
            for (int e = 0; e < NE; e++)
                if (srow[e] > best) { best = srow[e]; bi = e; }
            srow[bi] = -1.0f;
            out_w[j]   = best;
            out_idx[j] = (float)bi;
        }

        if (flag) {
            int i = atomicAdd(&s_nflag, 1);
            if (i < MAXFLAG) s_flags[i] = tid;
        }
    }
    __syncthreads();

    // ---- in-CTA exact fixup (serial fp32, split-K4 fold) ----
    const int nf = (s_nflag < MAXFLAG) ? s_nflag : MAXFLAG;
    if (nf > 0) {
        const int e  = tid & 63;
        const int sl = tid >> 6;            // slice 0..3
        const int slice = dim >> 2;         // 1024
        float* fixb = reinterpret_cast<float*>(dyn + SM_FIX);

        for (int f0 = 0; f0 < nf; f0 += 2) {
            const int f1 = (f0 + 1 < nf) ? f0 + 1 : f0;
            const float* xr0 = x + (size_t)(token0 + s_flags[f0]) * dim + sl * slice;
            const float* xr1 = x + (size_t)(token0 + s_flags[f1]) * dim + sl * slice;
            const float* wrp = w + (size_t)e * dim + sl * slice;
            float a0 = 0.0f, a1 = 0.0f;
            for (int k = 0; k < slice; k += 4) {
                float4 wv = *reinterpret_cast<const float4*>(wrp + k);
                float4 v0 = *reinterpret_cast<const float4*>(xr0 + k);
                float4 v1 = *reinterpret_cast<const float4*>(xr1 + k);
                a0 = fmaf(v0.x, wv.x, a0); a1 = fmaf(v1.x, wv.x, a1);
                a0 = fmaf(v0.y, wv.y, a0); a1 = fmaf(v1.y, wv.y, a1);
                a0 = fmaf(v0.z, wv.z, a0); a1 = fmaf(v1.z, wv.z, a1);
                a0 = fmaf(v0.w, wv.w, a0); a1 = fmaf(v1.w, wv.w, a1);
            }
            s_part[0][e * 4 + sl] = a0;
            s_part[1][e * 4 + sl] = a1;
            __syncthreads();
            if (tid < NE) {
                float t0 = ((s_part[0][tid * 4] + s_part[0][tid * 4 + 1])
                            + s_part[0][tid * 4 + 2]) + s_part[0][tid * 4 + 3];
                float t1 = ((s_part[1][tid * 4] + s_part[1][tid * 4 + 1])
                            + s_part[1][tid * 4 + 2]) + s_part[1][tid * 4 + 3];
                fixb[f0 * FSTR + tid] = t0;
                fixb[f1 * FSTR + tid] = t1;
            }
            __syncthreads();
        }

        if (tid < nf) {
            float* srow = fixb + tid * FSTR;
            float m = -FLT_MAX;
            for (int ee = 0; ee < NE; ee++) m = fmaxf(m, srow[ee]);
            float denom = 0.0f;
            for (int ee = 0; ee < NE; ee++) {
                float q = expf(srow[ee] - m);
                if (q < FLT_MIN) q = 0.0f;
                srow[ee] = q;
                denom += q;
            }
            float inv = 1.0f / denom;
            for (int ee = 0; ee < NE; ee++) {
                float q = srow[ee] * inv;
                if (q < FLT_MIN) q = 0.0f;
                srow[ee] = q;
            }
            const int tglob = token0 + s_flags[tid];
            float* out_w   = out + (size_t)tglob * TOPK;
            float* out_idx = out + (size_t)tokens * TOPK + (size_t)tglob * TOPK;
            for (int j = 0; j < TOPK; j++) {
                float best = -1.0f; int bi = 0;
                for (int ee = 0; ee < NE; ee++)
                    if (srow[ee] > best) { best = srow[ee]; bi = ee; }
                srow[bi] = -1.0f;
                out_w[j]   = best;
                out_idx[j] = (float)bi;
            }
        }
    }
}

// ================= launch =================
extern "C" void kernel_launch(void* const* d_in, const int* in_sizes, int n_in,
                              void* d_out, int out_size)
{
    const float* x = (const float*)d_in[0];
    const float* w = (const float*)d_in[1];
    // d_in[2] = bias: dead code in the reference

    const int num_experts = in_sizes[2];                 // 64
    const int dim         = in_sizes[1] / num_experts;   // 4096
    const int tokens      = in_sizes[0] / dim;           // 16384
    float* out = (float*)d_out;

    // idempotent, called every time (no static guards allowed)
    cudaFuncSetAttribute(gate_kernel,
                         cudaFuncAttributeMaxDynamicSharedMemorySize, SMEM_DYN);

    prep_w_kernel<<<128, 256>>>(w, dim);
    gate_kernel<<<tokens / TB, NT, SMEM_DYN>>>(x, w, out, dim, tokens);
}

// round 15
// speedup vs baseline: 1.0673x; 1.0673x over previous
#include <cuda_runtime.h>
#include <cuda_bf16.h>
#include <math.h>
#include <float.h>
#include <stdint.h>

// Gate_33827162423867 — fused HMMA router, 16-warp edition.
// R12 structure (3-stage cp.async.bulk ring for x, pre-converted/swizzled w
// tiles, bf16 2-split 3-product HMMA, FTZ softmax + top-8, knife-edge exact
// fixup) with NT=512: doubles warps/SM to hide the barrier-separated
// LDS/ldmatrix latency chains that capped every 8-warp variant at ~380us
// (DRAM was never >9% busy — the kernel is latency-bound, not BW-bound).
// Output: d_out float*, [0,T*8) gate weights, [T*8, 2*T*8) indices-as-float.

#define NE    64
#define TB    128
#define KCH   64
#define NT    512
#define TOPK  8

#define EPS_GAP 0.01f
#define EPS_B   0.01f
#define LN_FLT_MIN -87.33654475055310898657124730373f

#define RS    72       // bf16 x-tile row stride (elements); 144B rows
#define SSTR  65
#define FSTR  73
#define MAXFLAG 32

// smem layout (bytes) — same as R12
#define XSTRB 272                       // raw x row stride (256B data + 16B stagger)
#define XRS   (TB * XSTRB)              // 34816 per stage
#define XR(s) ((s) * XRS)
#define WR(s) (3 * XRS + (s) * 16384)   // wh 8KB + wl 8KB per stage
#define SM_XH (3 * XRS + 3 * 16384)     // 153600
#define SM_XL (SM_XH + 18432)           // 172032
#define SMEM_DYN (SM_XL + 18432)        // 190464
#define EXPECT_BYTES 49152
#define SM_FIX 65536                    // fixup rows (alias raw ring post-GEMM)

// pre-converted w tiles: 64 chunks x (8KB hi + 8KB lo), swizzled 128B rows
__device__ __align__(16) unsigned char g_wtiles[64 * 16384];

// ---------------- helpers ----------------
__device__ __forceinline__ uint32_t smem_u32(const void* p) {
    uint32_t a;
    asm("{ .reg .u64 t; cvta.to.shared.u64 t, %1; cvt.u32.u64 %0, t; }"
        : "=r"(a) : "l"(p));
    return a;
}
__device__ __forceinline__ uint32_t swz128(uint32_t b) {
    return b ^ ((b >> 3) & 0x70);
}
__device__ __forceinline__ uint32_t cvt_bf16x2(float lo, float hi) {
    uint32_t r;
    asm("cvt.rn.bf16x2.f32 %0, %1, %2;" : "=r"(r) : "f"(hi), "f"(lo));
    return r;
}
__device__ __forceinline__ float bflo_f(uint32_t h) { return __uint_as_float(h << 16); }
__device__ __forceinline__ float bfhi_f(uint32_t h) { return __uint_as_float(h & 0xFFFF0000u); }

__device__ __forceinline__ void mbar_init(uint32_t a, uint32_t cnt) {
    asm volatile("mbarrier.init.shared.b64 [%0], %1;" :: "r"(a), "r"(cnt) : "memory");
}
__device__ __forceinline__ void mbar_expect(uint32_t a, uint32_t bytes) {
    asm volatile("mbarrier.arrive.expect_tx.shared.b64 _, [%0], %1;"
                 :: "r"(a), "r"(bytes) : "memory");
}
__device__ __forceinline__ void mbar_wait(uint32_t a, uint32_t parity) {
    asm volatile(
        "{\n\t.reg .pred P1;\n\t"
        "WAIT_%=:\n\t"
        "mbarrier.try_wait.parity.acquire.cta.shared::cta.b64 P1, [%0], %1, 0x989680;\n\t"
        "@P1 bra.uni DONE_%=;\n\t"
        "bra.uni WAIT_%=;\n\t"
        "DONE_%=:\n\t}"
        :: "r"(a), "r"(parity) : "memory");
}
__device__ __forceinline__ void bulk_g2s(uint32_t dst, const void* src,
                                         uint32_t bytes, uint32_t mbar) {
    asm volatile(
        "cp.async.bulk.shared::cta.global.mbarrier::complete_tx::bytes "
        "[%0], [%1], %2, [%3];"
        :: "r"(dst), "l"(src), "r"(bytes), "r"(mbar) : "memory");
}
__device__ __forceinline__ void ldm_x4(uint32_t addr, uint32_t& r0, uint32_t& r1,
                                       uint32_t& r2, uint32_t& r3) {
    asm volatile("ldmatrix.sync.aligned.m8n8.x4.shared.b16 {%0,%1,%2,%3}, [%4];"
                 : "=r"(r0), "=r"(r1), "=r"(r2), "=r"(r3) : "r"(addr));
}
__device__ __forceinline__ void mma_bf16(float* d, uint32_t a0, uint32_t a1,
                                         uint32_t a2, uint32_t a3,
                                         uint32_t b0, uint32_t b1) {
    asm volatile(
        "mma.sync.aligned.m16n8k16.row.col.f32.bf16.bf16.f32 "
        "{%0,%1,%2,%3}, {%4,%5,%6,%7}, {%8,%9}, {%0,%1,%2,%3};"
        : "+f"(d[0]), "+f"(d[1]), "+f"(d[2]), "+f"(d[3])
        : "r"(a0), "r"(a1), "r"(a2), "r"(a3), "r"(b0), "r"(b1));
}

// ================= prep kernel: w -> swizzled bf16 hi/lo tiles =================
__global__ __launch_bounds__(256)
void prep_w_kernel(const float* __restrict__ w, int dim)
{
    // task: chunk c (64) x expert e (64) x 16B-block kb (8)
    int task = blockIdx.x * 256 + threadIdx.x;       // 0..32767
    int kb = task & 7;
    int e  = (task >> 3) & 63;
    int c  = task >> 9;
    const float* src = w + (size_t)e * dim + c * KCH + kb * 8;
    float v[8];
    #pragma unroll
    for (int i = 0; i < 8; i++) v[i] = src[i];
    uint32_t h[4], l[4];
    #pragma unroll
    for (int i = 0; i < 4; i++) {
        h[i] = cvt_bf16x2(v[2 * i], v[2 * i + 1]);
        l[i] = cvt_bf16x2(v[2 * i] - bflo_f(h[i]), v[2 * i + 1] - bfhi_f(h[i]));
    }
    uint32_t off = swz128((uint32_t)(e * 128 + kb * 16));
    unsigned char* base = g_wtiles + (size_t)c * 16384;
    *reinterpret_cast<uint4*>(base + off)        = make_uint4(h[0], h[1], h[2], h[3]);
    *reinterpret_cast<uint4*>(base + 8192 + off) = make_uint4(l[0], l[1], l[2], l[3]);
}

// ================= main fused kernel =================
__global__ __launch_bounds__(NT, 1)
void gate_kernel(const float* __restrict__ x,
                 const float* __restrict__ w,
                 float* __restrict__ out,
                 int dim, int tokens)
{
    extern __shared__ char dyn[];
    __shared__ __align__(8) uint64_t s_mbar[3];
    __shared__ int   s_nflag;
    __shared__ int   s_flags[MAXFLAG];
    __shared__ float s_part[2][4 * NE];

    const uint32_t sbase = smem_u32(dyn);
    const int tid  = threadIdx.x;
    const int wid  = tid >> 5;
    const int lane = tid & 31;
    const int token0 = blockIdx.x * TB;
    const int nchunks = dim / KCH;       // 64

    if (tid == 0) {
        s_nflag = 0;
        #pragma unroll
        for (int s = 0; s < 3; s++) mbar_init(smem_u32(&s_mbar[s]), 1);
        asm volatile("fence.proxy.async.shared::cta;" ::: "memory");
    }
    __syncthreads();

    uint32_t mb[3] = { smem_u32(&s_mbar[0]), smem_u32(&s_mbar[1]), smem_u32(&s_mbar[2]) };

    // issue stage s <- chunk c2
    auto issue = [&](int s, int c2) {
        if (tid < TB) {
            bulk_g2s(sbase + XR(s) + tid * XSTRB,
                     x + (size_t)(token0 + tid) * dim + c2 * KCH, 256, mb[s]);
        } else if (tid == TB) {
            bulk_g2s(sbase + WR(s), g_wtiles + (size_t)c2 * 16384, 16384, mb[s]);
        } else if (tid == TB + 1) {
            mbar_expect(mb[s], EXPECT_BYTES);
        }
    };

    // prologue: two stages in flight (stage 2 filled inside iter 0)
    issue(0, 0); issue(1, 1);

    // convert mapping: 512 threads, 128 rows x 64 floats -> 16 floats/thread
    const int crow = tid & 127;
    const int cg   = tid >> 7;           // 0..3 -> float cols cg*16..cg*16+15

    // MMA lane constants: 16 warps, warp = 16 tokens x 32 experts
    const int tg   = wid & 7;            // token group 0..7
    const int eh   = wid >> 3;           // expert half 0..1
    const int tokb = tg * 16;
    const uint32_t aoff = (uint32_t)((tokb + (lane & 7) + (((lane >> 3) & 1) * 8)) * (RS * 2)
                                     + ((lane >> 4) * 16));
    const int e_local = (lane & 7) + ((lane >> 4) << 3);
    const int colb    = ((lane >> 3) & 1) * 16;

    float acc[4][4];
    #pragma unroll
    for (int n = 0; n < 4; n++)
        #pragma unroll
        for (int i = 0; i < 4; i++) acc[n][i] = 0.0f;

    int ph[3] = {0, 0, 0};

    for (int c = 0; c < nchunks; c++) {
        const int s = c % 3;
        mbar_wait(mb[s], ph[s]); ph[s] ^= 1;
        __syncthreads();   // all warps done with chunk c-1 MMA (stage (c+2)%3 dead)

        // refill the dead stage with chunk c+2
        if (c + 2 < nchunks) issue((c + 2) % 3, c + 2);

        // ---- convert raw x (smem) -> bf16 hi/lo tiles (16 floats/thread) ----
        {
            const char* raw = dyn + XR(s) + crow * XSTRB + cg * 64;
            char* xh = dyn + SM_XH + crow * (RS * 2) + cg * 32;
            char* xl = dyn + SM_XL + crow * (RS * 2) + cg * 32;
            #pragma unroll
            for (int jj = 0; jj < 2; jj++) {       // 8 floats per iter
                float4 a = *reinterpret_cast<const float4*>(raw + jj * 32);
                float4 b = *reinterpret_cast<const float4*>(raw + jj * 32 + 16);
                uint32_t h0 = cvt_bf16x2(a.x, a.y);
                uint32_t h1 = cvt_bf16x2(a.z, a.w);
                uint32_t h2 = cvt_bf16x2(b.x, b.y);
                uint32_t h3 = cvt_bf16x2(b.z, b.w);
                uint32_t l0 = cvt_bf16x2(a.x - bflo_f(h0), a.y - bfhi_f(h0));
                uint32_t l1 = cvt_bf16x2(a.z - bflo_f(h1), a.w - bfhi_f(h1));
                uint32_t l2 = cvt_bf16x2(b.x - bflo_f(h2), b.y - bfhi_f(h2));
                uint32_t l3 = cvt_bf16x2(b.z - bflo_f(h3), b.w - bfhi_f(h3));
                *reinterpret_cast<uint4*>(xh + jj * 16) = make_uint4(h0, h1, h2, h3);
                *reinterpret_cast<uint4*>(xl + jj * 16) = make_uint4(l0, l1, l2, l3);
            }
        }
        __syncthreads();                 // bf16 x tiles ready

        // ---- MMA: 4 k-steps x 2 expert-pairs x 3 products (48 MMAs/warp) ----
        const uint32_t wbase = sbase + WR(s);
        #pragma unroll
        for (int ks = 0; ks < 4; ks++) {
            const uint32_t kb = (uint32_t)(ks * 32);
            uint32_t ah0, ah1, ah2, ah3, al0, al1, al2, al3;
            ldm_x4(sbase + SM_XH + aoff + kb, ah0, ah1, ah2, ah3);
            ldm_x4(sbase + SM_XL + aoff + kb, al0, al1, al2, al3);
            #pragma unroll
            for (int q = 0; q < 2; q++) {
                const int p = 2 * eh + q;
                uint32_t off = swz128((uint32_t)((p * 16 + e_local) * 128) + kb + (uint32_t)colb);
                uint32_t bh0, bh1, bh2, bh3, bl0, bl1, bl2, bl3;
                ldm_x4(wbase + off, bh0, bh1, bh2, bh3);
                ldm_x4(wbase + 8192 + off, bl0, bl1, bl2, bl3);
                mma_bf16(acc[2 * q], ah0, ah1, ah2, ah3, bh0, bh1);
                mma_bf16(acc[2 * q], ah0, ah1, ah2, ah3, bl0, bl1);
                mma_bf16(acc[2 * q], al0, al1, al2, al3, bh0, bh1);
                mma_bf16(acc[2 * q + 1], ah0, ah1, ah2, ah3, bh2, bh3);
                mma_bf16(acc[2 * q + 1], ah0, ah1, ah2, ah3, bl2, bl3);
                mma_bf16(acc[2 * q + 1], al0, al1, al2, al3, bh2, bh3);
            }
        }
    }

    __syncthreads();

    // ---- accumulators -> padded smem scores [128][SSTR] (alias raw ring) ----
    float* scores = reinterpret_cast<float*>(dyn);
    {
        const int g  = lane >> 2;
        const int t2 = (lane & 3) * 2;
        #pragma unroll
        for (int n = 0; n < 4; n++) {
            const int col = eh * 32 + n * 8 + t2;
            scores[(tokb + g) * SSTR + col]         = acc[n][0];
            scores[(tokb + g) * SSTR + col + 1]     = acc[n][1];
            scores[(tokb + g + 8) * SSTR + col]     = acc[n][2];
            scores[(tokb + g + 8) * SSTR + col + 1] = acc[n][3];
        }
    }
    __syncthreads();

    // ---- fast epilogue: 1 thread per token ----
    if (tid < TB) {
        float* srow = scores + tid * SSTR;
        float m = -FLT_MAX;
        #pragma unroll
        for (int e = 0; e < NE; e++) m = fmaxf(m, srow[e]);

        float denom = 0.0f;
        #pragma unroll
        for (int e = 0; e < NE; e++) {
            float q = __expf(srow[e] - m);
            if (q < FLT_MIN) q = 0.0f;
            denom += q;
        }

        bool flag = false;
        float b2 = LN_FLT_MIN + __logf(denom);
        #pragma unroll
        for (int e = 0; e < NE; e++) {
            float d = srow[e] - m;
            if (fabsf(d - LN_FLT_MIN) < EPS_B || fabsf(d - b2) < EPS_B) flag = true;
        }
        {
            unsigned long long used = 0ull;
            float prevv = 0.0f;
            for (int j = 0; j < 9; j++) {
                float best = -FLT_MAX; int bi = 0;
                for (int e = 0; e < NE; e++)
                    if (!((used >> e) & 1ull) && srow[e] > best) { best = srow[e]; bi = e; }
                used |= 1ull << bi;
                if (j > 0 && (prevv - best) < EPS_GAP) flag = true;
                prevv = best;
            }
        }

        float inv = 1.0f / denom;
        #pragma unroll
        for (int e = 0; e < NE; e++) {
            float q = __expf(srow[e] - m);
            if (q < FLT_MIN) q = 0.0f;
            q *= inv;
            if (q < FLT_MIN) q = 0.0f;
            srow[e] = q;
        }

        const int tglob = token0 + tid;
        float* out_w   = out + (size_t)tglob * TOPK;
        float* out_idx = out + (size_t)tokens * TOPK + (size_t)tglob * TOPK;
        #pragma unroll
        for (int j = 0; j < TOPK; j++) {
            float best = -1.0f; int bi = 0;
            for (int e = 0; e < NE; e++)
                if (srow[e] > best) { best = srow[e]; bi = e; }
            srow[bi] = -1.0f;
            out_w[j]   = best;
            out_idx[j] = (float)bi;
        }

        if (flag) {
            int i = atomicAdd(&s_nflag, 1);
            if (i < MAXFLAG) s_flags[i] = tid;
        }
    }
    __syncthreads();

    // ---- in-CTA exact fixup (serial fp32, split-K4 fold; first 256 threads) ----
    const int nf = (s_nflag < MAXFLAG) ? s_nflag : MAXFLAG;
    if (nf > 0) {
        const int e  = tid & 63;
        const int sl = (tid >> 6) & 3;      // slice 0..3
        const int slice = dim >> 2;         // 1024
        const bool active = (tid < 256);
        float* fixb = reinterpret_cast<float*>(dyn + SM_FIX);

        for (int f0 = 0; f0 < nf; f0 += 2) {
            const int f1 = (f0 + 1 < nf) ? f0 + 1 : f0;
            if (active) {
                const float* xr0 = x + (size_t)(token0 + s_flags[f0]) * dim + sl * slice;
                const float* xr1 = x + (size_t)(token0 + s_flags[f1]) * dim + sl * slice;
                const float* wrp = w + (size_t)e * dim + sl * slice;
                float a0 = 0.0f, a1 = 0.0f;
                for (int k = 0; k < slice; k += 4) {
                    float4 wv = *reinterpret_cast<const float4*>(wrp + k);
                    float4 v0 = *reinterpret_cast<const float4*>(xr0 + k);
                    float4 v1 = *reinterpret_cast<const float4*>(xr1 + k);
                    a0 = fmaf(v0.x, wv.x, a0); a1 = fmaf(v1.x, wv.x, a1);
                    a0 = fmaf(v0.y, wv.y, a0); a1 = fmaf(v1.y, wv.y, a1);
                    a0 = fmaf(v0.z, wv.z, a0); a1 = fmaf(v1.z, wv.z, a1);
                    a0 = fmaf(v0.w, wv.w, a0); a1 = fmaf(v1.w, wv.w, a1);
                }
                s_part[0][e * 4 + sl] = a0;
                s_part[1][e * 4 + sl] = a1;
            }
            __syncthreads();
            if (tid < NE) {
                float t0 = ((s_part[0][tid * 4] + s_part[0][tid * 4 + 1])
                            + s_part[0][tid * 4 + 2]) + s_part[0][tid * 4 + 3];
                float t1 = ((s_part[1][tid * 4] + s_part[1][tid * 4 + 1])
                            + s_part[1][tid * 4 + 2]) + s_part[1][tid * 4 + 3];
                fixb[f0 * FSTR + tid] = t0;
                fixb[f1 * FSTR + tid] = t1;
            }
            __syncthreads();
        }

        if (tid < nf) {
            float* srow = fixb + tid * FSTR;
            float m = -FLT_MAX;
            for (int ee = 0; ee < NE; ee++) m = fmaxf(m, srow[ee]);
            float denom = 0.0f;
            for (int ee = 0; ee < NE; ee++) {
                float q = expf(srow[ee] - m);
                if (q < FLT_MIN) q = 0.0f;
                srow[ee] = q;
                denom += q;
            }
            float inv = 1.0f / denom;
            for (int ee = 0; ee < NE; ee++) {
                float q = srow[ee] * inv;
                if (q < FLT_MIN) q = 0.0f;
                srow[ee] = q;
            }
            const int tglob = token0 + s_flags[tid];
            float* out_w   = out + (size_t)tglob * TOPK;
            float* out_idx = out + (size_t)tokens * TOPK + (size_t)tglob * TOPK;
            for (int j = 0; j < TOPK; j++) {
                float best = -1.0f; int bi = 0;
                for (int ee = 0; ee < NE; ee++)
                    if (srow[ee] > best) { best = srow[ee]; bi = ee; }
                srow[bi] = -1.0f;
                out_w[j]   = best;
                out_idx[j] = (float)bi;
            }
        }
    }
}

// ================= launch =================
extern "C" void kernel_launch(void* const* d_in, const int* in_sizes, int n_in,
                              void* d_out, int out_size)
{
    const float* x = (const float*)d_in[0];
    const float* w = (const float*)d_in[1];
    // d_in[2] = bias: dead code in the reference

    const int num_experts = in_sizes[2];                 // 64
    const int dim         = in_sizes[1] / num_experts;   // 4096
    const int tokens      = in_sizes[0] / dim;           // 16384
    float* out = (float*)d_out;

    // idempotent, called every time (no static guards allowed)
    cudaFuncSetAttribute(gate_kernel,
                         cudaFuncAttributeMaxDynamicSharedMemorySize, SMEM_DYN);

    prep_w_kernel<<<128, 256>>>(w, dim);
    gate_kernel<<<tokens / TB, NT, SMEM_DYN>>>(x, w, out, dim, tokens);
}